// round 2
// baseline (speedup 1.0000x reference)
#include <cuda_runtime.h>
#include <math.h>

// ---------------------------------------------------------------------------
// Problem constants
// ---------------------------------------------------------------------------
namespace {
constexpr int Bc = 64, Tc = 32, TMAX = 31;
constexpr int Fc = 512, Lc = 196, Ec = 512, Hc = 512, Ac = 512, Vc = 10000;
constexpr int NCAT = 3072;            // de(512) | fbeta(512) | hh gates(2048)
constexpr int XD   = 1024;            // E + F
constexpr long long PRED_SZ = (long long)Bc * TMAX * Vc;   // 19,840,000
}

// ---------------------------------------------------------------------------
// Scratch (static device memory — no allocations allowed)
// ---------------------------------------------------------------------------
__device__ float g_en_att[Bc * Lc * Ac];   // [B*L, A]  step-invariant attention keys
__device__ float g_meanf[Bc * Fc];
__device__ float g_h[Bc * Hc];
__device__ float g_c[Bc * Hc];
__device__ float g_hnew[Bc * Hc];
__device__ float g_hproj[Bc * NCAT];       // [B, de|fb|4H-gates]
__device__ float g_score[Bc * Lc];
__device__ float g_alpha[Bc * Lc];
__device__ float g_x[Bc * XD];             // [B, emb | z]
__device__ float g_Wcat[NCAT * Hc];        // [W_dec ; W_fbeta ; W_hh]
__device__ float g_bcat[NCAT];

// ---------------------------------------------------------------------------
// Build merged h-projection weight/bias (W_dec, W_fbeta, W_hh share input h)
// ---------------------------------------------------------------------------
__global__ void build_cat(const float* __restrict__ Wdec,
                          const float* __restrict__ Wfb,
                          const float* __restrict__ Whh,
                          const float* __restrict__ bdec,
                          const float* __restrict__ bfb,
                          const float* __restrict__ bih,
                          const float* __restrict__ bhh)
{
    int idx = blockIdx.x * 256 + threadIdx.x;
    if (idx < NCAT * Hc) {
        int n = idx / Hc, k = idx % Hc;
        float v;
        if (n < 512)       v = Wdec[n * Hc + k];
        else if (n < 1024) v = Wfb[(n - 512) * Hc + k];
        else               v = Whh[(n - 1024) * Hc + k];
        g_Wcat[idx] = v;
    }
    if (idx < NCAT) {
        float v;
        if (idx < 512)       v = bdec[idx];
        else if (idx < 1024) v = bfb[idx - 512];
        else                 v = bih[idx - 1024] + bhh[idx - 1024];
        g_bcat[idx] = v;
    }
}

// mean over the L axis of the ORIGINAL [B, F, L] layout
__global__ void mean_feat(const float* __restrict__ feat)
{
    int b = blockIdx.x, f = threadIdx.x;   // 512 threads
    const float* p = feat + (size_t)b * Fc * Lc + (size_t)f * Lc;
    float s = 0.f;
    #pragma unroll 4
    for (int l = 0; l < Lc; ++l) s += p[l];
    g_meanf[b * Fc + f] = s * (1.0f / (float)Lc);
}

// ---------------------------------------------------------------------------
// Generic fp32 NT GEMM:  C[M,N] = A[M,K] * B[N,K]^T (+bias)(+=C)(row mask->0)
//   BM=64, BK=16, TM=4; BN/TN templated (64/4 or 32/2), 256 threads.
// ---------------------------------------------------------------------------
template<int BN, int TN>
__global__ __launch_bounds__(256) void gemm_nt(
    int M, int N, int K,
    const float* __restrict__ Ap, const float* __restrict__ Bp,
    const float* __restrict__ bias, float* __restrict__ Cp, int ldC,
    int accFlag, const int* __restrict__ lengths, int step)
{
    constexpr int BM = 64, BK = 16, TM = 4;
    constexpr int TX = BN / TN;              // 16 in both configs
    const int bm = blockIdx.y * BM;
    const int bn = blockIdx.x * BN;

    __shared__ float As[BK][BM];
    __shared__ float Bs[BK][BN];

    const int tid = threadIdx.x;
    const int tx = tid % TX;                 // n direction
    const int ty = tid / TX;                 // m direction (0..15)

    float acc[TM][TN];
    #pragma unroll
    for (int i = 0; i < TM; ++i)
        #pragma unroll
        for (int j = 0; j < TN; ++j) acc[i][j] = 0.f;

    const int arow = tid / 4;                // 0..63
    const int acol = (tid % 4) * 4;          // 0,4,8,12

    for (int k0 = 0; k0 < K; k0 += BK) {
        // A tile (BM x BK), transposed store
        float4 av = *reinterpret_cast<const float4*>(
            Ap + (size_t)(bm + arow) * K + k0 + acol);
        As[acol + 0][arow] = av.x; As[acol + 1][arow] = av.y;
        As[acol + 2][arow] = av.z; As[acol + 3][arow] = av.w;

        // B tile (BN x BK), transposed store, row-guarded for N=10000
        if (BN == 64) {
            int br = tid / 4, bc = (tid % 4) * 4;
            int nrow = bn + br;
            float4 bv = make_float4(0.f, 0.f, 0.f, 0.f);
            if (nrow < N)
                bv = *reinterpret_cast<const float4*>(
                    Bp + (size_t)nrow * K + k0 + bc);
            Bs[bc + 0][br] = bv.x; Bs[bc + 1][br] = bv.y;
            Bs[bc + 2][br] = bv.z; Bs[bc + 3][br] = bv.w;
        } else {                              // BN == 32
            int br = tid / 8, bc = (tid % 8) * 2;
            int nrow = bn + br;
            float2 bv = make_float2(0.f, 0.f);
            if (nrow < N)
                bv = *reinterpret_cast<const float2*>(
                    Bp + (size_t)nrow * K + k0 + bc);
            Bs[bc + 0][br] = bv.x; Bs[bc + 1][br] = bv.y;
        }
        __syncthreads();

        #pragma unroll
        for (int k = 0; k < BK; ++k) {
            float a[TM], bb[TN];
            #pragma unroll
            for (int i = 0; i < TM; ++i) a[i] = As[k][ty * TM + i];
            #pragma unroll
            for (int j = 0; j < TN; ++j) bb[j] = Bs[k][tx * TN + j];
            #pragma unroll
            for (int i = 0; i < TM; ++i)
                #pragma unroll
                for (int j = 0; j < TN; ++j)
                    acc[i][j] += a[i] * bb[j];
        }
        __syncthreads();
    }

    #pragma unroll
    for (int i = 0; i < TM; ++i) {
        int m = bm + ty * TM + i;
        bool zero_row = false;
        if (lengths) zero_row = !((lengths[m] - 1) > step);
        #pragma unroll
        for (int j = 0; j < TN; ++j) {
            int col = bn + tx * TN + j;
            if (col < N) {
                float v = acc[i][j];
                if (bias) v += bias[col];
                float* cp = Cp + (size_t)m * ldC + col;
                if (accFlag) v += *cp;
                if (zero_row) v = 0.f;
                *cp = v;
            }
        }
    }
}

// ---------------------------------------------------------------------------
// Attention score: score[b,l] = sum_a tanh(en_att[b,l,a] + de[b,a]) * W_full[a]
// one warp per (b,l); de is g_hproj cols [0,512)
// ---------------------------------------------------------------------------
__global__ void att_score(const float* __restrict__ Wfull)
{
    int warp = threadIdx.x >> 5, lane = threadIdx.x & 31;
    int idx = blockIdx.x * 4 + warp;          // b*L + l
    int b = idx / Lc;
    const float* ea = g_en_att + (size_t)idx * Ac;
    const float* de = g_hproj + (size_t)b * NCAT;
    float s = 0.f;
    for (int a = lane; a < Ac; a += 32)
        s += tanhf(ea[a] + de[a]) * Wfull[a];
    #pragma unroll
    for (int o = 16; o > 0; o >>= 1) s += __shfl_xor_sync(0xffffffffu, s, o);
    if (lane == 0) g_score[idx] = s;
}

// softmax over L per batch row; writes unmasked alpha (for z) + masked output
__global__ void softmax_att(float* __restrict__ alpha_out,
                            const int* __restrict__ lengths, int step)
{
    int b = blockIdx.x, tid = threadIdx.x;    // 256 threads
    __shared__ float red[256];
    float v = (tid < Lc) ? g_score[b * Lc + tid] : -3.4e38f;
    red[tid] = v; __syncthreads();
    for (int s = 128; s > 0; s >>= 1) {
        if (tid < s) red[tid] = fmaxf(red[tid], red[tid + s]);
        __syncthreads();
    }
    float mx = red[0]; __syncthreads();
    float e = (tid < Lc) ? expf(v - mx) : 0.f;
    red[tid] = e; __syncthreads();
    for (int s = 128; s > 0; s >>= 1) {
        if (tid < s) red[tid] += red[tid + s];
        __syncthreads();
    }
    float inv = 1.f / red[0];
    if (tid < Lc) {
        float a = e * inv;
        g_alpha[b * Lc + tid] = a;
        bool act = (lengths[b] - 1) > step;
        alpha_out[((size_t)b * TMAX + step) * Lc + tid] = act ? a : 0.f;
    }
}

// embedding gather into x[:, 0:512]
__global__ void embed_step(const float* __restrict__ Wemb,
                           const int* __restrict__ captions, int step)
{
    int b = blockIdx.x, e = threadIdx.x;      // 512 threads
    int tok = captions[b * Tc + step];
    g_x[b * XD + e] = Wemb[(size_t)tok * Ec + e];
}

// z[b,f] = (sum_l feat_r[b,l,f] * alpha[b,l]) * sigmoid(fb[b,f]) -> x[:,512:]
__global__ void zgate(const float* __restrict__ feat)
{
    int b = blockIdx.x, f = threadIdx.x;      // 512 threads
    __shared__ float sa[Lc];
    if (f < Lc) sa[f] = g_alpha[b * Lc + f];
    __syncthreads();
    const float* fp = feat + (size_t)b * Lc * Fc + f;
    float acc = 0.f;
    #pragma unroll 4
    for (int l = 0; l < Lc; ++l) acc += fp[(size_t)l * Fc] * sa[l];
    float fb = g_hproj[(size_t)b * NCAT + 512 + f];
    float sg = 1.f / (1.f + expf(-fb));
    g_x[b * XD + 512 + f] = acc * sg;
}

// LSTM cell: gates live in g_hproj cols [1024, 3072)
__global__ void lstm_cell(const int* __restrict__ lengths, int step)
{
    int b = blockIdx.x, n = threadIdx.x;      // 512 threads
    const float* hp = g_hproj + (size_t)b * NCAT + 1024;
    float ig = hp[n], fg = hp[512 + n], gg = hp[1024 + n], og = hp[1536 + n];
    float c  = g_c[b * Hc + n];
    float si = 1.f / (1.f + expf(-ig));
    float sf = 1.f / (1.f + expf(-fg));
    float so = 1.f / (1.f + expf(-og));
    float cn = sf * c + si * tanhf(gg);
    float hn = so * tanhf(cn);
    g_hnew[b * Hc + n] = hn;
    if ((lengths[b] - 1) > step) {
        g_h[b * Hc + n] = hn;
        g_c[b * Hc + n] = cn;
    }
}

// ---------------------------------------------------------------------------
// Host driver (graph-capturable: kernel launches only)
// ---------------------------------------------------------------------------
extern "C" void kernel_launch(void* const* d_in, const int* in_sizes, int n_in,
                              void* d_out, int out_size)
{
    const float* features = (const float*)d_in[0];
    const int*   captions = (const int*)  d_in[1];
    const int*   lengths  = (const int*)  d_in[2];
    const float* W_emb    = (const float*)d_in[3];
    const float* W_enc    = (const float*)d_in[4];
    const float* b_enc    = (const float*)d_in[5];
    const float* W_dec    = (const float*)d_in[6];
    const float* b_dec    = (const float*)d_in[7];
    const float* W_full   = (const float*)d_in[8];
    /* d_in[9] = b_full: softmax shift-invariant, unused */
    const float* W_fbeta  = (const float*)d_in[10];
    const float* b_fbeta  = (const float*)d_in[11];
    const float* W_ih     = (const float*)d_in[12];
    const float* W_hh     = (const float*)d_in[13];
    const float* b_ih     = (const float*)d_in[14];
    const float* b_hh     = (const float*)d_in[15];
    const float* W_out    = (const float*)d_in[16];
    const float* b_out    = (const float*)d_in[17];
    const float* W_init_h = (const float*)d_in[18];
    const float* b_init_h = (const float*)d_in[19];
    const float* W_init_c = (const float*)d_in[20];
    const float* b_init_c = (const float*)d_in[21];

    float* out       = (float*)d_out;
    float* alpha_out = out + PRED_SZ;

    // Device addresses of scratch symbols (queries only — capture-safe)
    float *p_en_att, *p_meanf, *p_h, *p_c, *p_hnew, *p_hproj, *p_x, *p_Wcat, *p_bcat;
    cudaGetSymbolAddress((void**)&p_en_att, g_en_att);
    cudaGetSymbolAddress((void**)&p_meanf,  g_meanf);
    cudaGetSymbolAddress((void**)&p_h,      g_h);
    cudaGetSymbolAddress((void**)&p_c,      g_c);
    cudaGetSymbolAddress((void**)&p_hnew,   g_hnew);
    cudaGetSymbolAddress((void**)&p_hproj,  g_hproj);
    cudaGetSymbolAddress((void**)&p_x,      g_x);
    cudaGetSymbolAddress((void**)&p_Wcat,   g_Wcat);
    cudaGetSymbolAddress((void**)&p_bcat,   g_bcat);

    // ---- precompute -------------------------------------------------------
    build_cat<<<(NCAT * Hc + 255) / 256, 256>>>(W_dec, W_fbeta, W_hh,
                                                b_dec, b_fbeta, b_ih, b_hh);
    mean_feat<<<Bc, Fc>>>(features);
    gemm_nt<32, 2><<<dim3(Hc / 32, 1), 256>>>(Bc, Hc, Fc, p_meanf, W_init_h,
                                              b_init_h, p_h, Hc, 0, nullptr, 0);
    gemm_nt<32, 2><<<dim3(Hc / 32, 1), 256>>>(Bc, Hc, Fc, p_meanf, W_init_c,
                                              b_init_c, p_c, Hc, 0, nullptr, 0);
    gemm_nt<64, 4><<<dim3(Ac / 64, (Bc * Lc) / 64), 256>>>(
        Bc * Lc, Ac, Fc, features, W_enc, b_enc, p_en_att, Ac, 0, nullptr, 0);

    // ---- 31 recurrent steps ----------------------------------------------
    for (int t = 0; t < TMAX; ++t) {
        // all h-projections in one GEMM: de | sigmoid-gate pre | W_hh gates
        gemm_nt<32, 2><<<dim3(NCAT / 32, 1), 256>>>(
            Bc, NCAT, Hc, p_h, p_Wcat, p_bcat, p_hproj, NCAT, 0, nullptr, 0);

        att_score<<<(Bc * Lc) / 4, 128>>>(W_full);
        softmax_att<<<Bc, 256>>>(alpha_out, lengths, t);
        embed_step<<<Bc, Ec>>>(W_emb, captions, t);
        zgate<<<Bc, Fc>>>(features);

        // gates += x @ W_ih^T  (accumulates onto hproj cols [1024,3072))
        gemm_nt<32, 2><<<dim3(2048 / 32, 1), 256>>>(
            Bc, 2048, XD, p_x, W_ih, nullptr, p_hproj + 1024, NCAT, 1, nullptr, 0);

        lstm_cell<<<Bc, Hc>>>(lengths, t);

        // vocab projection from UNMASKED h_new, masked write into d_out
        gemm_nt<64, 4><<<dim3((Vc + 63) / 64, 1), 256>>>(
            Bc, Vc, Hc, p_hnew, W_out, b_out,
            out + (size_t)t * Vc, TMAX * Vc, 0, lengths, t);
    }
}

// round 3
// speedup vs baseline: 1.8709x; 1.8709x over previous
#include <cuda_runtime.h>
#include <math.h>

// ---------------------------------------------------------------------------
// Problem constants
// ---------------------------------------------------------------------------
namespace {
constexpr int Bc = 64, Tc = 32, TMAX = 31;
constexpr int Fc = 512, Lc = 196, Ec = 512, Hc = 512, Ac = 512, Vc = 10000;
constexpr int NCAT = 3072;            // de(512) | fbeta(512) | hh gates(2048)
constexpr long long PRED_SZ = (long long)Bc * TMAX * Vc;   // 19,840,000
}

// ---------------------------------------------------------------------------
// Static scratch (no allocations allowed)
// ---------------------------------------------------------------------------
__device__ float g_en_att[Bc * Lc * Ac];        // [B*L, A]
__device__ float g_meanf[Bc * Fc];
__device__ float g_h[Bc * Hc];
__device__ float g_c[Bc * Hc];
__device__ float g_hproj[Bc * NCAT];            // [B, de|fb|hh-gates]
__device__ float g_score[Bc * Lc];
__device__ float g_xz[Bc * Fc];                 // gated context z
__device__ float g_Wcat[NCAT * Hc];             // [W_dec ; W_fbeta ; W_hh]
__device__ float g_bcat[NCAT];
__device__ float g_xemb[TMAX * Bc * Ec];        // gathered embeddings (all steps)
__device__ float g_embg[TMAX * Bc * 2048];      // emb @ W_ih_emb^T (all steps)
__device__ float g_hnew_all[TMAX * Bc * Hc];    // unmasked h_new per step

__device__ __forceinline__ float tanh_fast(float x) {
    float y;
    asm("tanh.approx.f32 %0, %1;" : "=f"(y) : "f"(x));
    return y;
}
__device__ __forceinline__ float sigmoid_fast(float x) {
    return 1.0f / (1.0f + __expf(-x));
}

// ---------------------------------------------------------------------------
// Merged h-projection weight/bias
// ---------------------------------------------------------------------------
__global__ void build_cat(const float* __restrict__ Wdec,
                          const float* __restrict__ Wfb,
                          const float* __restrict__ Whh,
                          const float* __restrict__ bdec,
                          const float* __restrict__ bfb,
                          const float* __restrict__ bih,
                          const float* __restrict__ bhh)
{
    int idx = blockIdx.x * 256 + threadIdx.x;
    if (idx < NCAT * Hc) {
        int n = idx / Hc, k = idx % Hc;
        float v;
        if (n < 512)       v = Wdec[n * Hc + k];
        else if (n < 1024) v = Wfb[(n - 512) * Hc + k];
        else               v = Whh[(n - 1024) * Hc + k];
        g_Wcat[idx] = v;
    }
    if (idx < NCAT) {
        float v;
        if (idx < 512)       v = bdec[idx];
        else if (idx < 1024) v = bfb[idx - 512];
        else                 v = bih[idx - 1024] + bhh[idx - 1024];
        g_bcat[idx] = v;
    }
}

// mean over the L axis of the ORIGINAL [B, F, L] layout
__global__ void mean_feat(const float* __restrict__ feat)
{
    int b = blockIdx.x, f = threadIdx.x;   // 512 threads
    const float* p = feat + (size_t)b * Fc * Lc + (size_t)f * Lc;
    float s = 0.f;
    #pragma unroll 4
    for (int l = 0; l < Lc; ++l) s += p[l];
    g_meanf[b * Fc + f] = s * (1.0f / (float)Lc);
}

// gather embeddings for ALL steps at once
__global__ void embed_all(const float* __restrict__ Wemb,
                          const int* __restrict__ captions)
{
    int b = blockIdx.x, t = blockIdx.y, e = threadIdx.x;   // 512 threads
    int tok = captions[b * Tc + t];
    g_xemb[((size_t)t * Bc + b) * Ec + e] = Wemb[(size_t)tok * Ec + e];
}

// ---------------------------------------------------------------------------
// Double-buffered fp32 NT GEMM: C[M,N] = A[M,K] * B[N,K]^T  (+bias)
//   BM=64 fixed, 256 threads. mode: 0 = store, 1 = accumulate onto C,
//   2 = vocab scatter: row m -> (t = m/64, b = m%64), masked by lengths.
//   K must be a multiple of 16; M a multiple of 64.
// ---------------------------------------------------------------------------
template<int BN, int TM, int TN>
__global__ __launch_bounds__(256) void gemm2(
    int M, int N, int K,
    const float* __restrict__ Ap, const float* __restrict__ Bp, int ldB,
    const float* __restrict__ bias, float* __restrict__ Cp, int ldC,
    int mode, const int* __restrict__ lengths, float* __restrict__ predBase)
{
    constexpr int BM = 64, BK = 16;
    constexpr int TX = BN / TN;
    constexpr int TY = BM / TM;
    static_assert(TX * TY == 256, "bad tiling");

    __shared__ float As[2][BK][BM];
    __shared__ float Bs[2][BK][BN];

    const int tid = threadIdx.x;
    const int tx = tid % TX, ty = tid / TX;
    const int bm = blockIdx.y * BM, bn = blockIdx.x * BN;

    // loader indices
    const int arow = tid >> 2, acol = (tid & 3) * 4;   // A: one float4/thread
    int brow, bcol;
    if (BN == 64) { brow = tid >> 2; bcol = (tid & 3) * 4; }
    else          { brow = tid >> 3; bcol = (tid & 7) * 2; }

    const float* aptr = Ap + (size_t)(bm + arow) * K + acol;
    const float* bptr = Bp + (size_t)(bn + brow) * ldB + bcol;
    const bool bvalid = (bn + brow) < N;

    float acc[TM][TN];
    #pragma unroll
    for (int i = 0; i < TM; ++i)
        #pragma unroll
        for (int j = 0; j < TN; ++j) acc[i][j] = 0.f;

    float4 av, bv4;
    float2 bv2;

    // preload tile 0
    av = *reinterpret_cast<const float4*>(aptr);
    if (BN == 64) {
        bv4 = bvalid ? *reinterpret_cast<const float4*>(bptr)
                     : make_float4(0.f, 0.f, 0.f, 0.f);
    } else {
        bv2 = bvalid ? *reinterpret_cast<const float2*>(bptr)
                     : make_float2(0.f, 0.f);
    }
    As[0][acol + 0][arow] = av.x; As[0][acol + 1][arow] = av.y;
    As[0][acol + 2][arow] = av.z; As[0][acol + 3][arow] = av.w;
    if (BN == 64) {
        Bs[0][bcol + 0][brow] = bv4.x; Bs[0][bcol + 1][brow] = bv4.y;
        Bs[0][bcol + 2][brow] = bv4.z; Bs[0][bcol + 3][brow] = bv4.w;
    } else {
        Bs[0][bcol + 0][brow] = bv2.x; Bs[0][bcol + 1][brow] = bv2.y;
    }
    __syncthreads();

    const int nt = K / BK;
    for (int it = 0; it < nt; ++it) {
        const int cur = it & 1;
        if (it + 1 < nt) {
            av = *reinterpret_cast<const float4*>(aptr + (it + 1) * BK);
            if (BN == 64) {
                bv4 = bvalid ? *reinterpret_cast<const float4*>(bptr + (it + 1) * BK)
                             : make_float4(0.f, 0.f, 0.f, 0.f);
            } else {
                bv2 = bvalid ? *reinterpret_cast<const float2*>(bptr + (it + 1) * BK)
                             : make_float2(0.f, 0.f);
            }
        }
        #pragma unroll
        for (int k = 0; k < BK; ++k) {
            float ar[TM], br[TN];
            if (TM == 4) {
                float4 t4 = *reinterpret_cast<const float4*>(&As[cur][k][ty * TM]);
                ar[0] = t4.x; ar[1] = t4.y; ar[2] = t4.z; ar[3] = t4.w;
            } else {
                float2 t2 = *reinterpret_cast<const float2*>(&As[cur][k][ty * TM]);
                ar[0] = t2.x; ar[1] = t2.y;
            }
            {
                float4 t4 = *reinterpret_cast<const float4*>(&Bs[cur][k][tx * TN]);
                br[0] = t4.x; br[1] = t4.y; br[2] = t4.z; br[3] = t4.w;
            }
            #pragma unroll
            for (int i = 0; i < TM; ++i)
                #pragma unroll
                for (int j = 0; j < TN; ++j)
                    acc[i][j] += ar[i] * br[j];
        }
        if (it + 1 < nt) {
            const int nxt = cur ^ 1;
            As[nxt][acol + 0][arow] = av.x; As[nxt][acol + 1][arow] = av.y;
            As[nxt][acol + 2][arow] = av.z; As[nxt][acol + 3][arow] = av.w;
            if (BN == 64) {
                Bs[nxt][bcol + 0][brow] = bv4.x; Bs[nxt][bcol + 1][brow] = bv4.y;
                Bs[nxt][bcol + 2][brow] = bv4.z; Bs[nxt][bcol + 3][brow] = bv4.w;
            } else {
                Bs[nxt][bcol + 0][brow] = bv2.x; Bs[nxt][bcol + 1][brow] = bv2.y;
            }
        }
        __syncthreads();
    }

    #pragma unroll
    for (int i = 0; i < TM; ++i) {
        const int m = bm + ty * TM + i;
        float* dst;
        bool zero_row = false;
        if (mode == 2) {
            const int b = m & 63, t = m >> 6;
            zero_row = !((lengths[b] - 1) > t);
            dst = predBase + ((size_t)b * TMAX + t) * Vc;
        } else {
            dst = Cp + (size_t)m * ldC;
        }
        #pragma unroll
        for (int j = 0; j < TN; ++j) {
            const int col = bn + tx * TN + j;
            if (col < N) {
                float v = acc[i][j];
                if (bias) v += bias[col];
                if (mode == 1) v += dst[col];
                if (zero_row) v = 0.f;
                dst[col] = v;
            }
        }
    }
}

// ---------------------------------------------------------------------------
// score[b,l] = sum_a tanh(en_att[b,l,a] + de[b,a]) * W_full[a]
// ---------------------------------------------------------------------------
__global__ void att_score(const float* __restrict__ Wfull)
{
    int warp = threadIdx.x >> 5, lane = threadIdx.x & 31;
    int idx = blockIdx.x * 8 + warp;          // b*L + l
    int b = idx / Lc;
    const float* ea = g_en_att + (size_t)idx * Ac;
    const float* de = g_hproj + (size_t)b * NCAT;
    float s = 0.f;
    #pragma unroll 4
    for (int a = lane; a < Ac; a += 32)
        s += tanh_fast(ea[a] + de[a]) * Wfull[a];
    #pragma unroll
    for (int o = 16; o > 0; o >>= 1) s += __shfl_xor_sync(0xffffffffu, s, o);
    if (lane == 0) g_score[idx] = s;
}

// ---------------------------------------------------------------------------
// Fused softmax over L + gated context z (one block per b, 256 threads)
// ---------------------------------------------------------------------------
__global__ void softmax_zgate(const float* __restrict__ feat,
                              float* __restrict__ alpha_out,
                              const int* __restrict__ lengths, int step)
{
    int b = blockIdx.x, tid = threadIdx.x;
    __shared__ float red[256];
    __shared__ float sa[Lc];

    float v = (tid < Lc) ? g_score[b * Lc + tid] : -3.4e38f;
    red[tid] = v; __syncthreads();
    for (int s = 128; s > 0; s >>= 1) {
        if (tid < s) red[tid] = fmaxf(red[tid], red[tid + s]);
        __syncthreads();
    }
    float mx = red[0]; __syncthreads();
    float e = (tid < Lc) ? __expf(v - mx) : 0.f;
    red[tid] = e; __syncthreads();
    for (int s = 128; s > 0; s >>= 1) {
        if (tid < s) red[tid] += red[tid + s];
        __syncthreads();
    }
    float inv = 1.f / red[0];
    if (tid < Lc) {
        float a = e * inv;
        sa[tid] = a;
        bool act = (lengths[b] - 1) > step;
        alpha_out[((size_t)b * TMAX + step) * Lc + tid] = act ? a : 0.f;
    }
    __syncthreads();

    // z[b,f] = (sum_l feat_r[b,l,f] * alpha[b,l]) * sigmoid(fb[b,f])
    const float* fp = feat + (size_t)b * Lc * Fc;
    int f0 = tid, f1 = tid + 256;
    float a0 = 0.f, a1 = 0.f;
    #pragma unroll 4
    for (int l = 0; l < Lc; ++l) {
        float al = sa[l];
        a0 += fp[(size_t)l * Fc + f0] * al;
        a1 += fp[(size_t)l * Fc + f1] * al;
    }
    float fb0 = g_hproj[(size_t)b * NCAT + 512 + f0];
    float fb1 = g_hproj[(size_t)b * NCAT + 512 + f1];
    g_xz[b * Fc + f0] = a0 * sigmoid_fast(fb0);
    g_xz[b * Fc + f1] = a1 * sigmoid_fast(fb1);
}

// ---------------------------------------------------------------------------
// LSTM cell; gates = g_hproj[1024:] (h@Whh + z@Wihz + biases) + embgates[t]
// ---------------------------------------------------------------------------
__global__ void lstm_cell(const int* __restrict__ lengths, int step)
{
    int b = blockIdx.x, n = threadIdx.x;      // 512 threads
    const float* hp = g_hproj + (size_t)b * NCAT + 1024;
    const float* eg = g_embg + ((size_t)step * Bc + b) * 2048;
    float ig = hp[n]        + eg[n];
    float fg = hp[512 + n]  + eg[512 + n];
    float gg = hp[1024 + n] + eg[1024 + n];
    float og = hp[1536 + n] + eg[1536 + n];
    float c  = g_c[b * Hc + n];
    float si = sigmoid_fast(ig);
    float sf = sigmoid_fast(fg);
    float so = sigmoid_fast(og);
    float cn = sf * c + si * tanhf(gg);
    float hn = so * tanhf(cn);
    g_hnew_all[((size_t)step * Bc + b) * Hc + n] = hn;
    if ((lengths[b] - 1) > step) {
        g_h[b * Hc + n] = hn;
        g_c[b * Hc + n] = cn;
    }
}

// ---------------------------------------------------------------------------
// Host driver (graph-capturable: kernel launches only)
// ---------------------------------------------------------------------------
extern "C" void kernel_launch(void* const* d_in, const int* in_sizes, int n_in,
                              void* d_out, int out_size)
{
    const float* features = (const float*)d_in[0];
    const int*   captions = (const int*)  d_in[1];
    const int*   lengths  = (const int*)  d_in[2];
    const float* W_emb    = (const float*)d_in[3];
    const float* W_enc    = (const float*)d_in[4];
    const float* b_enc    = (const float*)d_in[5];
    const float* W_dec    = (const float*)d_in[6];
    const float* b_dec    = (const float*)d_in[7];
    const float* W_full   = (const float*)d_in[8];
    /* d_in[9] = b_full: softmax shift-invariant, unused */
    const float* W_fbeta  = (const float*)d_in[10];
    const float* b_fbeta  = (const float*)d_in[11];
    const float* W_ih     = (const float*)d_in[12];
    const float* W_hh     = (const float*)d_in[13];
    const float* b_ih     = (const float*)d_in[14];
    const float* b_hh     = (const float*)d_in[15];
    const float* W_out    = (const float*)d_in[16];
    const float* b_out    = (const float*)d_in[17];
    const float* W_init_h = (const float*)d_in[18];
    const float* b_init_h = (const float*)d_in[19];
    const float* W_init_c = (const float*)d_in[20];
    const float* b_init_c = (const float*)d_in[21];

    float* out       = (float*)d_out;
    float* alpha_out = out + PRED_SZ;

    float *p_en_att, *p_meanf, *p_h, *p_c, *p_hproj, *p_xz,
          *p_Wcat, *p_bcat, *p_xemb, *p_embg, *p_hnew_all;
    cudaGetSymbolAddress((void**)&p_en_att,   g_en_att);
    cudaGetSymbolAddress((void**)&p_meanf,    g_meanf);
    cudaGetSymbolAddress((void**)&p_h,        g_h);
    cudaGetSymbolAddress((void**)&p_c,        g_c);
    cudaGetSymbolAddress((void**)&p_hproj,    g_hproj);
    cudaGetSymbolAddress((void**)&p_xz,       g_xz);
    cudaGetSymbolAddress((void**)&p_Wcat,     g_Wcat);
    cudaGetSymbolAddress((void**)&p_bcat,     g_bcat);
    cudaGetSymbolAddress((void**)&p_xemb,     g_xemb);
    cudaGetSymbolAddress((void**)&p_embg,     g_embg);
    cudaGetSymbolAddress((void**)&p_hnew_all, g_hnew_all);

    // ---- precompute -------------------------------------------------------
    build_cat<<<(NCAT * Hc + 255) / 256, 256>>>(W_dec, W_fbeta, W_hh,
                                                b_dec, b_fbeta, b_ih, b_hh);
    mean_feat<<<Bc, Fc>>>(features);
    embed_all<<<dim3(Bc, TMAX), Ec>>>(W_emb, captions);

    // h0, c0
    gemm2<32, 2, 4><<<dim3(Hc / 32, 1), 256>>>(
        Bc, Hc, Fc, p_meanf, W_init_h, Fc, b_init_h, p_h, Hc, 0, nullptr, nullptr);
    gemm2<32, 2, 4><<<dim3(Hc / 32, 1), 256>>>(
        Bc, Hc, Fc, p_meanf, W_init_c, Fc, b_init_c, p_c, Hc, 0, nullptr, nullptr);

    // embedding gates for all steps: [1984, 2048] = xemb @ W_ih[:, 0:512]^T
    gemm2<64, 4, 4><<<dim3(2048 / 64, TMAX), 256>>>(
        TMAX * Bc, 2048, Ec, p_xemb, W_ih, Ec + Fc, nullptr,
        p_embg, 2048, 0, nullptr, nullptr);

    // attention keys: [12544, 512] = feat_r @ W_enc^T
    gemm2<64, 4, 4><<<dim3(Ac / 64, (Bc * Lc) / 64), 256>>>(
        Bc * Lc, Ac, Fc, features, W_enc, Fc, b_enc,
        p_en_att, Ac, 0, nullptr, nullptr);

    // ---- 31 recurrent steps (critical path only) --------------------------
    for (int t = 0; t < TMAX; ++t) {
        // h projections: de | fbeta-pre | hh-gates (with b_ih+b_hh baked in)
        gemm2<32, 2, 4><<<dim3(NCAT / 32, 1), 256>>>(
            Bc, NCAT, Hc, p_h, p_Wcat, Hc, p_bcat, p_hproj, NCAT,
            0, nullptr, nullptr);

        att_score<<<(Bc * Lc) / 8, 256>>>(W_full);
        softmax_zgate<<<Bc, 256>>>(features, alpha_out, lengths, t);

        // gates += z @ W_ih[:, 512:1024]^T
        gemm2<32, 2, 4><<<dim3(2048 / 32, 1), 256>>>(
            Bc, 2048, Fc, p_xz, W_ih + Fc, Ec + Fc, nullptr,
            p_hproj + 1024, NCAT, 1, nullptr, nullptr);

        lstm_cell<<<Bc, Hc>>>(lengths, t);
    }

    // ---- batched vocab projection for all 31 steps (off critical path) ----
    gemm2<64, 4, 4><<<dim3((Vc + 63) / 64, TMAX), 256>>>(
        TMAX * Bc, Vc, Hc, p_hnew_all, W_out, Hc, b_out,
        nullptr, 0, 2, lengths, out);
}